// round 4
// baseline (speedup 1.0000x reference)
#include <cuda_runtime.h>
#include <cstdint>

// Problem dims
#define DSZ   256
#define QL    64
#define PL    128
#define BATCH 64
#define TWO_D 512
#define FOUR_D 1024
#define LDW   33280   // (Q+1)*2D

// ---------------- scratch (device globals; allocation-free) ----------------
__device__ float g_Sp[PL * BATCH * DSZ];        // H_p @ Wa^T + ba          [P,B,D]
__device__ float g_ga[QL * BATCH * DSZ];        // H_q @ Wg^T               [Q,B,D]
__device__ float g_Xp[PL * BATCH * FOUR_D];     // H_p @ Wih_p^T + biases   [P,B,4D]
__device__ float g_U [QL * BATCH * FOUR_D];     // per-q Hq @ Wih_q^T       [Q,B,4D]
__device__ float g_WbT [DSZ * DSZ];             // Wb^T  [k][d]
__device__ float g_WhhT[DSZ * FOUR_D];          // Whh^T [k][n]

// ---------------- transpose: out[c*R + r] = in[r*C + c] --------------------
__global__ void transpose_k(const float* __restrict__ in, float* __restrict__ out,
                            int R, int C)
{
    __shared__ float tile[32][33];
    int r0 = blockIdx.y * 32, c0 = blockIdx.x * 32;
    int x = threadIdx.x, y = threadIdx.y;       // block (32, 8)
#pragma unroll
    for (int i = 0; i < 32; i += 8)
        tile[y + i][x] = in[(long)(r0 + y + i) * C + c0 + x];
    __syncthreads();
#pragma unroll
    for (int i = 0; i < 32; i += 8)
        out[(long)(c0 + y + i) * R + r0 + x] = tile[x][y + i];
}

// ---------------- merged NT SGEMM: 4 problems in one launch ----------------
#define BM 64
#define BN 128
#define BKK 16

struct GD {
    const float* A; const float* B; float* C;
    const float* b1; const float* b2;
    int lda, ldb, ldc, K, nx, ny, base;
    long Az, Bz, Cz;
};
struct GPack { GD d[4]; };

__global__ __launch_bounds__(256) void gemm_nt_multi(GPack P)
{
    __shared__ float As[BKK][BM];
    __shared__ float Bs[BKK][BN];
    const int bid = blockIdx.x;
    int i = 3;
    if (bid < P.d[1].base) i = 0;
    else if (bid < P.d[2].base) i = 1;
    else if (bid < P.d[3].base) i = 2;
    const GD g = P.d[i];
    const int local = bid - g.base;
    const int per_z = g.nx * g.ny;
    const int z  = local / per_z;
    const int rm = local % per_z;
    const int by = rm / g.nx;
    const int bx = rm % g.nx;

    const int t  = threadIdx.x;
    const int m0 = by * BM;
    const int n0 = bx * BN;
    const float* A = g.A + (long)z * g.Az + (long)m0 * g.lda;
    const float* B = g.B + (long)z * g.Bz + (long)n0 * g.ldb;
    float*       C = g.C + (long)z * g.Cz;
    const int K = g.K, lda = g.lda, ldb = g.ldb, ldc = g.ldc;

    const int arow = t >> 2, akq = t & 3;
    const int tx = t & 31, ty = t >> 5;

    float acc[8][4];
#pragma unroll
    for (int a = 0; a < 8; a++)
#pragma unroll
        for (int j = 0; j < 4; j++) acc[a][j] = 0.f;

    for (int k0 = 0; k0 < K; k0 += BKK) {
        float4 av = *(const float4*)(A + (long)arow * lda + k0 + akq * 4);
        As[akq * 4 + 0][arow] = av.x;
        As[akq * 4 + 1][arow] = av.y;
        As[akq * 4 + 2][arow] = av.z;
        As[akq * 4 + 3][arow] = av.w;
#pragma unroll
        for (int q = 0; q < 2; q++) {
            int idx = t * 2 + q;
            int brow = idx >> 2, bkq = idx & 3;
            float4 bv = *(const float4*)(B + (long)brow * ldb + k0 + bkq * 4);
            Bs[bkq * 4 + 0][brow] = bv.x;
            Bs[bkq * 4 + 1][brow] = bv.y;
            Bs[bkq * 4 + 2][brow] = bv.z;
            Bs[bkq * 4 + 3][brow] = bv.w;
        }
        __syncthreads();
#pragma unroll
        for (int k = 0; k < BKK; k++) {
            float4 a0 = *(const float4*)&As[k][ty * 8];
            float4 a1 = *(const float4*)&As[k][ty * 8 + 4];
            float4 bb = *(const float4*)&Bs[k][tx * 4];
            float am[8] = {a0.x, a0.y, a0.z, a0.w, a1.x, a1.y, a1.z, a1.w};
            float bv[4] = {bb.x, bb.y, bb.z, bb.w};
#pragma unroll
            for (int a = 0; a < 8; a++)
#pragma unroll
                for (int j = 0; j < 4; j++) acc[a][j] += am[a] * bv[j];
        }
        __syncthreads();
    }

#pragma unroll
    for (int a = 0; a < 8; a++) {
        int m = m0 + ty * 8 + a;
#pragma unroll
        for (int j = 0; j < 4; j++) {
            int n = n0 + tx * 4 + j;
            float v = acc[a][j];
            if (g.b1) v += g.b1[n];
            if (g.b2) v += g.b2[n];
            C[(long)m * ldc + n] = v;
        }
    }
}

// ---------------- recurrent scan: 8-CTA clusters, SMEM-resident weights ----
__device__ __forceinline__ float tanh_fast(float x) {
    float y;
    asm("tanh.approx.f32 %0, %1;" : "=f"(y) : "f"(x));
    return y;
}
__device__ __forceinline__ float sigmoidf_(float x) {
    return 1.f / (1.f + __expf(-x));
}
__device__ __forceinline__ uint32_t smem_u32(const void* p) {
    uint32_t a;
    asm("{ .reg .u64 tt; cvta.to.shared.u64 tt, %1; cvt.u32.u64 %0, tt; }"
        : "=r"(a) : "l"(p));
    return a;
}
__device__ __forceinline__ uint32_t my_ctarank() {
    uint32_t r;
    asm("mov.u32 %0, %%cluster_ctarank;" : "=r"(r));
    return r;
}
__device__ __forceinline__ void st_remote_f32(uint32_t laddr, uint32_t rank, float v) {
    asm volatile(
        "{ .reg .b32 ra; mapa.shared::cluster.u32 ra, %0, %1; "
        "st.shared::cluster.f32 [ra], %2; }"
        :: "r"(laddr), "r"(rank), "f"(v) : "memory");
}
__device__ __forceinline__ void cluster_sync_() {
    asm volatile("barrier.cluster.arrive.aligned;" ::: "memory");
    asm volatile("barrier.cluster.wait.aligned;" ::: "memory");
}

// SMEM layout (float offsets)
#define OFF_WHH  0                 // [256][128]  32768
#define OFF_WB   32768             // [256][32]    8192
#define OFF_GA   40960             // [4b][32d][64q] 8192
#define OFF_H    49152             // [2][4b][256] 2048
#define OFF_PART 51200             // 2560 (phase A: [8kp][4b][32d]; B: [5][4b][128])
#define OFF_LP   53760             // [8r][4b][64q] 2048
#define OFF_AL   55808             // [4b][64q]     256
#define OFF_S    56064             // [4b][32d]     128
#define OFF_C    56192             // [4b][32d]     128
#define OFF_AW   56320             // [32]           32
#define OFF_RED  56352             // 16
#define SMEM_FLOATS 56368
#define SMEM_BYTES  (SMEM_FLOATS * 4)

__global__ void __cluster_dims__(8, 1, 1) __launch_bounds__(256, 1)
recurrent_cluster(const float* __restrict__ h0, const float* __restrict__ c0,
                  const float* __restrict__ alpha_w, float* __restrict__ out)
{
    extern __shared__ float sm[];
    const int tid = threadIdx.x;
    const int lane = tid & 31;
    const uint32_t r = my_ctarank();
    const int b0 = (blockIdx.x >> 3) * 4;

    const uint32_t base_u32 = smem_u32(sm);

    // ---- load resident slices ----
    // WhhT slice: whh[k][j], j = g*32+d -> global n = g*256 + 32r + d
    for (int idx = tid; idx < 256 * 128; idx += 256) {
        int k = idx >> 7, j = idx & 127;
        int jg = (j >> 5) * 256 + 32 * r + (j & 31);
        sm[OFF_WHH + idx] = g_WhhT[k * FOUR_D + jg];
    }
    // WbT slice: wb[k][d] = WbT[k][32r+d]
    for (int idx = tid; idx < 256 * 32; idx += 256) {
        int k = idx >> 5, d = idx & 31;
        sm[OFF_WB + idx] = g_WbT[k * DSZ + 32 * r + d];
    }
    // ga slice: [b][d][q]
    for (int idx = tid; idx < 4 * 32 * 64; idx += 256) {
        int b = idx >> 11, d = (idx >> 6) & 31, q = idx & 63;
        sm[OFF_GA + idx] = g_ga[((long)q * BATCH + b0 + b) * DSZ + 32 * r + d];
    }
    // h, c, aw
    for (int idx = tid; idx < 4 * 256; idx += 256) {
        int b = idx >> 8, k = idx & 255;
        sm[OFF_H + idx] = h0[(b0 + b) * DSZ + k];
    }
    if (tid < 128) {
        int b = tid >> 5, d = tid & 31;
        sm[OFF_C + tid] = c0[(b0 + b) * DSZ + 32 * r + d];
    }
    if (tid < 32) sm[OFF_AW + tid] = alpha_w[32 * r + tid];
    __syncthreads();
    cluster_sync_();

    for (int t = 0; t < PL; t++) {
        const int cur = t & 1, nxt = cur ^ 1;
        const float* hb = sm + OFF_H + cur * 1024;

        // ---- Phase A: s-partials: thread (kp = tid>>5 in [0,8), d = tid&31) ----
        {
            const int kp = tid >> 5, d = tid & 31;
            float a0 = 0.f, a1 = 0.f, a2 = 0.f, a3 = 0.f;
            const float* wbp = sm + OFF_WB + d;
#pragma unroll
            for (int i4 = 0; i4 < 8; i4++) {
                int k = kp * 32 + i4 * 4;
                float4 h0v = *(const float4*)(hb + 0 * 256 + k);
                float4 h1v = *(const float4*)(hb + 1 * 256 + k);
                float4 h2v = *(const float4*)(hb + 2 * 256 + k);
                float4 h3v = *(const float4*)(hb + 3 * 256 + k);
                const float* h0a = (const float*)&h0v;
                const float* h1a = (const float*)&h1v;
                const float* h2a = (const float*)&h2v;
                const float* h3a = (const float*)&h3v;
#pragma unroll
                for (int ii = 0; ii < 4; ii++) {
                    float w = wbp[(k + ii) * 32];
                    a0 += h0a[ii] * w; a1 += h1a[ii] * w;
                    a2 += h2a[ii] * w; a3 += h3a[ii] * w;
                }
            }
            sm[OFF_PART + kp * 128 + 0 * 32 + d] = a0;
            sm[OFF_PART + kp * 128 + 1 * 32 + d] = a1;
            sm[OFF_PART + kp * 128 + 2 * 32 + d] = a2;
            sm[OFF_PART + kp * 128 + 3 * 32 + d] = a3;
        }
        __syncthreads();

        // ---- s reduce (128 threads) ----
        if (tid < 128) {
            const int d = tid & 31, b = tid >> 5;
            float v = g_Sp[((long)t * BATCH + b0 + b) * DSZ + 32 * r + d];
#pragma unroll
            for (int kp = 0; kp < 8; kp++) v += sm[OFF_PART + kp * 128 + b * 32 + d];
            sm[OFF_S + b * 32 + d] = v;
        }
        __syncthreads();

        // ---- logits partial: thread (q = tid&63, b = tid>>6); publish to all ----
        {
            const int q = tid & 63, b = tid >> 6;
            const float* gap = sm + OFF_GA + b * 2048 + q;
            const float* sp  = sm + OFF_S + b * 32;
            const float* aw  = sm + OFF_AW;
            float lp = 0.f;
#pragma unroll
            for (int d = 0; d < 32; d++)
                lp += tanh_fast(gap[d * 64] + sp[d]) * aw[d];
            uint32_t laddr = base_u32 + (OFF_LP + r * 256 + b * 64 + q) * 4;
#pragma unroll
            for (uint32_t p = 0; p < 8; p++) st_remote_f32(laddr, p, lp);
        }
        cluster_sync_();   // LP slices visible in every CTA

        // ---- softmax (redundant per CTA): thread (q, b) ----
        {
            const int q = tid & 63, b = tid >> 6;
            const int half = (tid >> 5) & 1;
            float v = 0.f;
#pragma unroll
            for (int rr = 0; rr < 8; rr++) v += sm[OFF_LP + rr * 256 + b * 64 + q];
            float m = v;
#pragma unroll
            for (int o = 16; o > 0; o >>= 1) m = fmaxf(m, __shfl_xor_sync(0xffffffffu, m, o));
            if (lane == 0) sm[OFF_RED + b * 2 + half] = m;
            __syncthreads();
            float M = fmaxf(sm[OFF_RED + b * 2], sm[OFF_RED + b * 2 + 1]);
            float e = __expf(v - M);
            float s = e;
#pragma unroll
            for (int o = 16; o > 0; o >>= 1) s += __shfl_xor_sync(0xffffffffu, s, o);
            __syncthreads();
            if (lane == 0) sm[OFF_RED + b * 2 + half] = s;
            __syncthreads();
            float S = sm[OFF_RED + b * 2] + sm[OFF_RED + b * 2 + 1];
            sm[OFF_AL + b * 64 + q] = e / S;
        }

        // ---- Phase B1: Whh partials: thread (kp2 = tid>>6 in [0,4), n2 = tid&63) ----
        const int kp2 = tid >> 6, n2 = tid & 63;
        float2 a0 = {0.f, 0.f}, a1 = {0.f, 0.f}, a2 = {0.f, 0.f}, a3 = {0.f, 0.f};
        {
            const float2* whh2 = (const float2*)(sm + OFF_WHH) + n2;
#pragma unroll
            for (int i4 = 0; i4 < 16; i4++) {
                int k = kp2 * 64 + i4 * 4;
                float4 h0v = *(const float4*)(hb + 0 * 256 + k);
                float4 h1v = *(const float4*)(hb + 1 * 256 + k);
                float4 h2v = *(const float4*)(hb + 2 * 256 + k);
                float4 h3v = *(const float4*)(hb + 3 * 256 + k);
                const float* h0a = (const float*)&h0v;
                const float* h1a = (const float*)&h1v;
                const float* h2a = (const float*)&h2v;
                const float* h3a = (const float*)&h3v;
#pragma unroll
                for (int ii = 0; ii < 4; ii++) {
                    float2 w = whh2[(k + ii) * 64];
                    a0.x += h0a[ii] * w.x; a0.y += h0a[ii] * w.y;
                    a1.x += h1a[ii] * w.x; a1.y += h1a[ii] * w.y;
                    a2.x += h2a[ii] * w.x; a2.y += h2a[ii] * w.y;
                    a3.x += h3a[ii] * w.x; a3.y += h3a[ii] * w.y;
                }
            }
        }
        __syncthreads();   // alpha published; partA fully consumed
        {
            float2* pb = (float2*)(sm + OFF_PART + kp2 * 512);
            pb[0 * 64 + n2] = a0;
            pb[1 * 64 + n2] = a1;
            pb[2 * 64 + n2] = a2;
            pb[3 * 64 + n2] = a3;
        }

        // ---- Phase B2: U + Xp: thread (b2 = tid>>6, n2) ----
        {
            const int b2 = tid >> 6;
            const int gg = n2 >> 4, d2 = (n2 & 15) * 2;
            const int nglob = gg * 256 + 32 * r + d2;
            float2 acc = __ldg((const float2*)(g_Xp + ((long)t * BATCH + b0 + b2) * FOUR_D + nglob));
            const float2* u2 = (const float2*)(g_U + (long)(b0 + b2) * FOUR_D + nglob);
            const float* al = sm + OFF_AL + b2 * 64;
#pragma unroll 8
            for (int q = 0; q < QL; q++) {
                float a = al[q];
                float2 u = __ldg(u2 + (long)q * (BATCH * FOUR_D / 2));
                acc.x += a * u.x; acc.y += a * u.y;
            }
            ((float2*)(sm + OFF_PART + 4 * 512 + b2 * 128))[n2] = acc;
        }
        __syncthreads();

        // ---- LSTM cell (128 threads) + h broadcast to all CTAs ----
        if (tid < 128) {
            const int d = tid & 31, b = tid >> 5;
            float gi = 0.f, gf = 0.f, gc = 0.f, go = 0.f;
#pragma unroll
            for (int p = 0; p < 5; p++) {
                const float* pp = sm + OFF_PART + p * 512 + b * 128;
                gi += pp[d]; gf += pp[32 + d]; gc += pp[64 + d]; go += pp[96 + d];
            }
            float c = sigmoidf_(gf) * sm[OFF_C + b * 32 + d] + sigmoidf_(gi) * tanhf(gc);
            float hn = sigmoidf_(go) * tanhf(c);
            sm[OFF_C + b * 32 + d] = c;
            out[((long)t * BATCH + b0 + b) * DSZ + 32 * r + d] = hn;
            uint32_t haddr = base_u32 + (OFF_H + nxt * 1024 + b * 256 + 32 * r + d) * 4;
#pragma unroll
            for (uint32_t p = 0; p < 8; p++) st_remote_f32(haddr, p, hn);
        }
        cluster_sync_();   // next-step h visible in every CTA
    }
}

// ---------------- launch ----------------
extern "C" void kernel_launch(void* const* d_in, const int* in_sizes, int n_in,
                              void* d_out, int out_size)
{
    const float* H_p     = (const float*)d_in[0];
    const float* h_ri    = (const float*)d_in[1];
    const float* H_q     = (const float*)d_in[2];
    const float* hidden  = (const float*)d_in[3];
    const float* Wa      = (const float*)d_in[4];
    const float* ba      = (const float*)d_in[5];
    const float* Wb      = (const float*)d_in[6];
    const float* Wg      = (const float*)d_in[7];
    const float* alpha_w = (const float*)d_in[8];
    const float* W_ih    = (const float*)d_in[10];
    const float* W_hh    = (const float*)d_in[11];
    const float* b_ih    = (const float*)d_in[12];
    const float* b_hh    = (const float*)d_in[13];
    float* out = (float*)d_out;

    float *Sp, *ga, *Xp, *U, *WbT, *WhhT;
    cudaGetSymbolAddress((void**)&Sp, g_Sp);
    cudaGetSymbolAddress((void**)&ga, g_ga);
    cudaGetSymbolAddress((void**)&Xp, g_Xp);
    cudaGetSymbolAddress((void**)&U,  g_U);
    cudaGetSymbolAddress((void**)&WbT,  g_WbT);
    cudaGetSymbolAddress((void**)&WhhT, g_WhhT);

    cudaFuncSetAttribute(recurrent_cluster,
                         cudaFuncAttributeMaxDynamicSharedMemorySize, SMEM_BYTES);

    dim3 tb(32, 8);
    transpose_k<<<dim3(DSZ / 32, DSZ / 32), tb>>>(Wb, WbT, DSZ, DSZ);
    transpose_k<<<dim3(DSZ / 32, FOUR_D / 32), tb>>>(W_hh, WhhT, FOUR_D, DSZ);

    GPack P;
    // Sp = H_p @ Wa^T + ba : M=8192, N=256, K=512
    P.d[0] = { H_p, Wa, Sp, ba, nullptr, TWO_D, TWO_D, DSZ, TWO_D,
               2, 128, 0, 0, 0, 0 };
    // ga = H_q @ Wg^T : M=4096, N=256
    P.d[1] = { H_q, Wg, ga, nullptr, nullptr, TWO_D, TWO_D, DSZ, TWO_D,
               2, 64, 256, 0, 0, 0 };
    // Xp = H_p @ W_ih[:, :512]^T + b_ih + b_hh : M=8192, N=1024
    P.d[2] = { H_p, W_ih, Xp, b_ih, b_hh, TWO_D, LDW, FOUR_D, TWO_D,
               8, 128, 384, 0, 0, 0 };
    // U[q] = H_q[q] @ W_ih[:, 512(q+1):512(q+2)]^T : 64 z, M=64, N=1024
    P.d[3] = { H_q, W_ih + TWO_D, U, nullptr, nullptr, TWO_D, LDW, FOUR_D, TWO_D,
               8, 1, 1408, (long)BATCH * TWO_D, (long)TWO_D, (long)BATCH * FOUR_D };
    gemm_nt_multi<<<1920, 256>>>(P);

    recurrent_cluster<<<128, 256, SMEM_BYTES>>>(h_ri, hidden, alpha_w, out);
}